// round 1
// baseline (speedup 1.0000x reference)
#include <cuda_runtime.h>
#include <math.h>

#define NB   128
#define NHID 512
#define GATE_ELEMS (NB * NHID)   // 65536

// ---------------- device scratch (no allocations allowed) ----------------
__device__ float d_gpre[GATE_ELEMS];
__device__ float d_rpre[GATE_ELEMS];
__device__ float d_av  [GATE_ELEMS];   // 1 - g
__device__ float d_cgv [GATE_ELEMS];   // dg * delta_h
__device__ float d_crv [GATE_ELEMS];   // dr * g
__device__ float d_hv  [GATE_ELEMS];   // new h
__device__ float d_ppre[GATE_ELEMS];
__device__ float d_opre[GATE_ELEMS];
__device__ int   d_open;

__global__ void k_zero() { d_open = 0; }

// ---------------------------------------------------------------------------
// Fused dual GEMM: C[128, 1024] = A[128,1024] @ W[1024,1024]^T + bias
//  A cols [0,512) come from Ax, [512,1024) from Ah (phase0: h_last, phase1: d_hv)
//  W rows n<512 use (W1x|W1h)/b1 -> out1 ; n>=512 use (W2x|W2h)/b2 -> out2
//  phase 0: out1=d_gpre, out2=d_rpre.  phase 1: out1=d_ppre, out2=d_opre.
// Tiles: BM=BN=BK=32, 256 threads, 2x2 register tile. grid = (32, 4) = 128 CTAs.
// ---------------------------------------------------------------------------
__global__ void __launch_bounds__(256) k_gemm(
    const float* __restrict__ Ax, const float* __restrict__ Ah_in,
    const float* __restrict__ W1x, const float* __restrict__ W1h, const float* __restrict__ b1,
    const float* __restrict__ W2x, const float* __restrict__ W2h, const float* __restrict__ b2,
    int phase)
{
    __shared__ float As[32][33];   // [k][m], padded: conflict-free stores & broadcast reads
    __shared__ float Ws[32][33];   // [n][k], padded

    const float* Ah  = phase ? d_hv  : Ah_in;
    float* out1      = phase ? d_ppre : d_gpre;
    float* out2      = phase ? d_opre : d_rpre;

    const int tid = threadIdx.x;
    const int m0  = blockIdx.y * 32;
    const int n0  = blockIdx.x * 32;          // n in [0,1024)
    const bool g2 = (n0 >= 512);
    const float* Wx   = g2 ? W2x : W1x;
    const float* Wh   = g2 ? W2h : W1h;
    const float* bias = g2 ? b2  : b1;
    float* outp       = g2 ? out2 : out1;
    const int j0      = g2 ? (n0 - 512) : n0;

    const int tx = tid & 15;       // n-dir
    const int ty = tid >> 4;       // m-dir
    const int lm = tid >> 3;       // 0..31 : tile row to load
    const int lk = (tid & 7) << 2; // 0,4,...,28 : k offset (float4)

    float acc00 = 0.f, acc01 = 0.f, acc10 = 0.f, acc11 = 0.f;

    for (int kt = 0; kt < 1024; kt += 32) {
        const float* Asrc = (kt < 512) ? Ax : Ah;
        const float* Wsrc = (kt < 512) ? Wx : Wh;
        const int kb = (kt < 512) ? kt : (kt - 512);

        float4 av = *(const float4*)(Asrc + (m0 + lm) * 512 + kb + lk);
        float4 wv = *(const float4*)(Wsrc + (j0 + lm) * 512 + kb + lk);

        __syncthreads();
        As[lk + 0][lm] = av.x; As[lk + 1][lm] = av.y;
        As[lk + 2][lm] = av.z; As[lk + 3][lm] = av.w;
        Ws[lm][lk + 0] = wv.x; Ws[lm][lk + 1] = wv.y;
        Ws[lm][lk + 2] = wv.z; Ws[lm][lk + 3] = wv.w;
        __syncthreads();

        #pragma unroll
        for (int kk = 0; kk < 32; kk++) {
            float a0 = As[kk][ty];
            float a1 = As[kk][ty + 16];
            float w0 = Ws[tx][kk];
            float w1 = Ws[tx + 16][kk];
            acc00 = fmaf(a0, w0, acc00);
            acc01 = fmaf(a0, w1, acc01);
            acc10 = fmaf(a1, w0, acc10);
            acc11 = fmaf(a1, w1, acc11);
        }
    }

    const float bj0 = bias[j0 + tx];
    const float bj1 = bias[j0 + tx + 16];
    outp[(m0 + ty)      * 512 + j0 + tx]      = acc00 + bj0;
    outp[(m0 + ty)      * 512 + j0 + tx + 16] = acc01 + bj1;
    outp[(m0 + ty + 16) * 512 + j0 + tx]      = acc10 + bj0;
    outp[(m0 + ty + 16) * 512 + j0 + tx + 16] = acc11 + bj1;
}

// ---------------------------------------------------------------------------
// Gate epilogue: per (b,j) compute g, r, h, trace coefficients, e_b updates,
// and the openings count (integer atomic -> deterministic).
// ---------------------------------------------------------------------------
__global__ void __launch_bounds__(256) k_gates(
    const float* __restrict__ h_last,
    const float* __restrict__ e_b_g, const float* __restrict__ e_b_r,
    float* __restrict__ out_h, float* __restrict__ out_ebg, float* __restrict__ out_ebr)
{
    const int idx = blockIdx.x * 256 + threadIdx.x;
    float g = tanhf(d_gpre[idx]);
    g = fmaxf(g, 0.f);                      // relu(tanh)
    const float r  = tanhf(d_rpre[idx]);
    const float hl = h_last[idx];
    const float h  = g * r + (1.f - g) * hl;
    const float Hg = (g > 0.f) ? 1.f : 0.f; // clip(ceil(g),0,1), g in [0,1]
    const float dg = (1.f - g * g) * Hg;
    const float dr = 1.f - r * r;
    const float delta = r - hl;
    const float a  = 1.f - g;
    const float cg = dg * delta;
    const float cr = dr * g;

    d_av[idx]  = a;
    d_cgv[idx] = cg;
    d_crv[idx] = cr;
    d_hv[idx]  = h;

    out_h[idx]   = h;
    out_ebg[idx] = e_b_g[idx] * a + cg;
    out_ebr[idx] = e_b_r[idx] * a + cr;

    const int cnt = __popc(__ballot_sync(0xffffffffu, g > 0.f));
    if ((threadIdx.x & 31) == 0) atomicAdd(&d_open, cnt);
}

// out = sigmoid(o_pre) * tanh(p_pre)
__global__ void __launch_bounds__(256) k_out(float* __restrict__ out)
{
    const int idx = blockIdx.x * 256 + threadIdx.x;
    const float p = tanhf(d_ppre[idx]);
    const float o = 1.f / (1.f + expf(-d_opre[idx]));
    out[idx] = o * p;
}

__global__ void k_open(float* __restrict__ o)
{
    o[0] = (float)d_open * (1.f / (float)GATE_ELEMS);
}

// ---------------------------------------------------------------------------
// Trace streamer: the HBM-bound kernel. One thread = one float4 column chunk
// of one (b,j) row, applied to all 4 trace tensors.
//   e_gx' = e_gx*a + cg*x[i];  e_gh' = e_gh*a + cg*hl[i]
//   e_rx' = e_rx*a + cr*x[i];  e_rh' = e_rh*a + cr*hl[i]
// ---------------------------------------------------------------------------
__global__ void __launch_bounds__(256) k_traces(
    const float* __restrict__ x,  const float* __restrict__ hl,
    const float* __restrict__ egx, const float* __restrict__ egh,
    const float* __restrict__ erx, const float* __restrict__ erh,
    float* __restrict__ ogx, float* __restrict__ ogh,
    float* __restrict__ orx, float* __restrict__ orh)
{
    const int idx = blockIdx.x * 256 + threadIdx.x;   // 8388608 threads
    const int i   = (idx & 127) << 2;                 // column (float4 aligned)
    const int bj  = idx >> 7;                         // (b,j) flat
    const int b   = bj >> 9;

    const float a  = __ldg(&d_av[bj]);                // uniform per warp -> broadcast
    const float cg = __ldg(&d_cgv[bj]);
    const float cr = __ldg(&d_crv[bj]);

    const float4 xv = *(const float4*)(x  + (b << 9) + i);
    const float4 hv = *(const float4*)(hl + (b << 9) + i);
    const int off = (bj << 9) + i;

    float4 e, t;

    e = *(const float4*)(egx + off);
    t.x = e.x * a + cg * xv.x; t.y = e.y * a + cg * xv.y;
    t.z = e.z * a + cg * xv.z; t.w = e.w * a + cg * xv.w;
    *(float4*)(ogx + off) = t;

    e = *(const float4*)(egh + off);
    t.x = e.x * a + cg * hv.x; t.y = e.y * a + cg * hv.y;
    t.z = e.z * a + cg * hv.z; t.w = e.w * a + cg * hv.w;
    *(float4*)(ogh + off) = t;

    e = *(const float4*)(erx + off);
    t.x = e.x * a + cr * xv.x; t.y = e.y * a + cr * xv.y;
    t.z = e.z * a + cr * xv.z; t.w = e.w * a + cr * xv.w;
    *(float4*)(orx + off) = t;

    e = *(const float4*)(erh + off);
    t.x = e.x * a + cr * hv.x; t.y = e.y * a + cr * hv.y;
    t.z = e.z * a + cr * hv.z; t.w = e.w * a + cr * hv.w;
    *(float4*)(orh + off) = t;
}

// ---------------------------------------------------------------------------
extern "C" void kernel_launch(void* const* d_in, const int* in_sizes, int n_in,
                              void* d_out, int out_size)
{
    const float* x      = (const float*)d_in[0];
    const float* h_last = (const float*)d_in[1];
    const float* w_gx   = (const float*)d_in[2];
    const float* w_gh   = (const float*)d_in[3];
    const float* b_g    = (const float*)d_in[4];
    const float* w_rx   = (const float*)d_in[5];
    const float* w_rh   = (const float*)d_in[6];
    const float* b_r    = (const float*)d_in[7];
    const float* w_px   = (const float*)d_in[8];
    const float* w_ph   = (const float*)d_in[9];
    const float* b_p    = (const float*)d_in[10];
    const float* w_ox   = (const float*)d_in[11];
    const float* w_oh   = (const float*)d_in[12];
    const float* b_o    = (const float*)d_in[13];
    const float* e_w_gx = (const float*)d_in[14];
    const float* e_w_gh = (const float*)d_in[15];
    const float* e_b_g  = (const float*)d_in[16];
    const float* e_w_rx = (const float*)d_in[17];
    const float* e_w_rh = (const float*)d_in[18];
    const float* e_b_r  = (const float*)d_in[19];

    float* out    = (float*)d_out;
    float* o_out  = out;                  // (128,512)
    float* o_h    = out + 65536;          // (128,512)
    float* o_egx  = out + 131072;         // (128,512,512)
    float* o_egh  = out + 33685504;       // (128,512,512)
    float* o_ebg  = out + 67239936;       // (128,512)
    float* o_erx  = out + 67305472;       // (128,512,512)
    float* o_erh  = out + 100859904;      // (128,512,512)
    float* o_ebr  = out + 134414336;      // (128,512)
    float* o_open = out + 134479872;      // scalar

    k_zero<<<1, 1>>>();

    // g/r pre-activations
    k_gemm<<<dim3(32, 4), 256>>>(x, h_last,
                                 w_gx, w_gh, b_g,
                                 w_rx, w_rh, b_r, /*phase=*/0);

    // gate math, h, e_b updates, openings count
    k_gates<<<GATE_ELEMS / 256, 256>>>(h_last, e_b_g, e_b_r, o_h, o_ebg, o_ebr);

    // p/o pre-activations (uses d_hv computed above)
    k_gemm<<<dim3(32, 4), 256>>>(x, h_last /*ignored*/,
                                 w_px, w_ph, b_p,
                                 w_ox, w_oh, b_o, /*phase=*/1);

    k_out<<<GATE_ELEMS / 256, 256>>>(o_out);
    k_open<<<1, 1>>>(o_open);

    // HBM-bound trace streamer: 128*512*512/4 = 8.39M threads
    k_traces<<<(NB * NHID * (NHID / 4)) / 256, 256>>>(
        x, h_last, e_w_gx, e_w_gh, e_w_rx, e_w_rh,
        o_egx, o_egh, o_erx, o_erh);
}

// round 2
// speedup vs baseline: 1.2172x; 1.2172x over previous
#include <cuda_runtime.h>
#include <math.h>

#define NB   128
#define NHID 512
#define GATE_ELEMS (NB * NHID)   // 65536
#define NSPLIT 4

// ---------------- device scratch (no allocations allowed) ----------------
__device__ float d_part[NSPLIT][NB * 1024];  // split-K partials, 2 MB
__device__ float d_av  [GATE_ELEMS];         // 1 - g
__device__ float d_cgv [GATE_ELEMS];         // dg * delta_h
__device__ float d_crv [GATE_ELEMS];         // dr * g
__device__ float d_hv  [GATE_ELEMS];         // new h
__device__ int   d_open;

__global__ void k_zero() { d_open = 0; }

// ---------------------------------------------------------------------------
// Split-K dual GEMM: partial[s][128,1024] += A[128, k-chunk] @ W[1024, k-chunk]^T
//   Logical C[128,1024]: A cols [0,512)=Ax, [512,1024)=Ah; W rows n<512 use
//   (W1x|W1h), n>=512 use (W2x|W2h). No bias here (added in epilogue).
// Tiles: BM=BN=64, BK=16, splitK=4 (chunk 256 = entirely within one k-half).
// 256 threads, 4x4 register tile, LDS.128 operand reads, register prefetch.
// grid = (16 n-tiles, 2 m-tiles, 4 splits) = 128 CTAs.
// ---------------------------------------------------------------------------
__global__ void __launch_bounds__(256) k_gemm(
    const float* __restrict__ Ax, const float* __restrict__ Ah_in,
    const float* __restrict__ W1x, const float* __restrict__ W1h,
    const float* __restrict__ W2x, const float* __restrict__ W2h,
    int phase)
{
    __shared__ float As[16][68];   // [k][m], stride 68 floats (272B = 16B-mult)
    __shared__ float Ws[16][68];   // [k][n]

    const int tid  = threadIdx.x;
    const int n0   = blockIdx.x * 64;       // n in [0,1024)
    const int m0   = blockIdx.y * 64;
    const int s    = blockIdx.z;            // split 0..3
    const int half = s >> 1;                 // 0: x-part, 1: h-part
    const int kb   = (s & 1) * 256;          // offset within the 512-wide half

    const bool g2 = (n0 >= 512);
    const int  j0 = g2 ? (n0 - 512) : n0;
    const float* A = half ? (phase ? d_hv : Ah_in) : Ax;
    const float* W = g2 ? (half ? W2h : W2x) : (half ? W1h : W1x);
    float* outp    = d_part[s];

    // loader mapping: one float4 of A and of W per thread per k-tile
    const int lm  = tid & 63;                // tile row (m or n)
    const int lk4 = (tid >> 6) << 2;         // k offset 0,4,8,12

    // compute mapping: 16x16 threads, 4x4 outputs each
    const int tx = tid & 15;                 // n-dir
    const int ty = tid >> 4;                 // m-dir

    const float* Aload = A + (m0 + lm) * 512 + kb + lk4;
    const float* Wload = W + (j0 + lm) * 512 + kb + lk4;

    float acc[4][4];
    #pragma unroll
    for (int i = 0; i < 4; i++)
        #pragma unroll
        for (int j = 0; j < 4; j++) acc[i][j] = 0.f;

    float4 av = *(const float4*)(Aload);
    float4 wv = *(const float4*)(Wload);

    for (int kt = 0; kt < 256; kt += 16) {
        __syncthreads();
        As[lk4 + 0][lm] = av.x; As[lk4 + 1][lm] = av.y;
        As[lk4 + 2][lm] = av.z; As[lk4 + 3][lm] = av.w;
        Ws[lk4 + 0][lm] = wv.x; Ws[lk4 + 1][lm] = wv.y;
        Ws[lk4 + 2][lm] = wv.z; Ws[lk4 + 3][lm] = wv.w;
        __syncthreads();

        if (kt + 16 < 256) {                 // prefetch next tile (overlaps compute)
            av = *(const float4*)(Aload + kt + 16);
            wv = *(const float4*)(Wload + kt + 16);
        }

        #pragma unroll
        for (int kk = 0; kk < 16; kk++) {
            const float4 a = *(const float4*)&As[kk][ty << 2];
            const float4 w = *(const float4*)&Ws[kk][tx << 2];
            acc[0][0] = fmaf(a.x, w.x, acc[0][0]);
            acc[0][1] = fmaf(a.x, w.y, acc[0][1]);
            acc[0][2] = fmaf(a.x, w.z, acc[0][2]);
            acc[0][3] = fmaf(a.x, w.w, acc[0][3]);
            acc[1][0] = fmaf(a.y, w.x, acc[1][0]);
            acc[1][1] = fmaf(a.y, w.y, acc[1][1]);
            acc[1][2] = fmaf(a.y, w.z, acc[1][2]);
            acc[1][3] = fmaf(a.y, w.w, acc[1][3]);
            acc[2][0] = fmaf(a.z, w.x, acc[2][0]);
            acc[2][1] = fmaf(a.z, w.y, acc[2][1]);
            acc[2][2] = fmaf(a.z, w.z, acc[2][2]);
            acc[2][3] = fmaf(a.z, w.w, acc[2][3]);
            acc[3][0] = fmaf(a.w, w.x, acc[3][0]);
            acc[3][1] = fmaf(a.w, w.y, acc[3][1]);
            acc[3][2] = fmaf(a.w, w.z, acc[3][2]);
            acc[3][3] = fmaf(a.w, w.w, acc[3][3]);
        }
    }

    #pragma unroll
    for (int i = 0; i < 4; i++) {
        float4 v = make_float4(acc[i][0], acc[i][1], acc[i][2], acc[i][3]);
        *(float4*)(outp + (m0 + (ty << 2) + i) * 1024 + n0 + (tx << 2)) = v;
    }
}

// ---------------------------------------------------------------------------
// Gate epilogue: sum split-K partials, add bias, compute g, r, h, trace
// coefficients, e_b updates, openings count (integer atomic -> deterministic).
// ---------------------------------------------------------------------------
__global__ void __launch_bounds__(256) k_gates(
    const float* __restrict__ h_last,
    const float* __restrict__ b_g, const float* __restrict__ b_r,
    const float* __restrict__ e_b_g, const float* __restrict__ e_b_r,
    float* __restrict__ out_h, float* __restrict__ out_ebg, float* __restrict__ out_ebr)
{
    const int idx = blockIdx.x * 256 + threadIdx.x;   // b*512 + j
    const int b = idx >> 9;
    const int j = idx & 511;
    const int og = b * 1024 + j;
    const int orr = og + 512;

    float gpre = b_g[j] + d_part[0][og] + d_part[1][og] + d_part[2][og] + d_part[3][og];
    float rpre = b_r[j] + d_part[0][orr] + d_part[1][orr] + d_part[2][orr] + d_part[3][orr];

    float g = tanhf(gpre);
    g = fmaxf(g, 0.f);                      // relu(tanh)
    const float r  = tanhf(rpre);
    const float hl = h_last[idx];
    const float h  = g * r + (1.f - g) * hl;
    const float Hg = (g > 0.f) ? 1.f : 0.f; // clip(ceil(g),0,1), g in [0,1]
    const float dg = (1.f - g * g) * Hg;
    const float dr = 1.f - r * r;
    const float delta = r - hl;
    const float a  = 1.f - g;
    const float cg = dg * delta;
    const float cr = dr * g;

    d_av[idx]  = a;
    d_cgv[idx] = cg;
    d_crv[idx] = cr;
    d_hv[idx]  = h;

    out_h[idx]   = h;
    out_ebg[idx] = e_b_g[idx] * a + cg;
    out_ebr[idx] = e_b_r[idx] * a + cr;

    const int cnt = __popc(__ballot_sync(0xffffffffu, g > 0.f));
    if ((threadIdx.x & 31) == 0) atomicAdd(&d_open, cnt);
}

// out = sigmoid(o_pre) * tanh(p_pre), summing split-K partials + bias
__global__ void __launch_bounds__(256) k_out(
    const float* __restrict__ b_p, const float* __restrict__ b_o,
    float* __restrict__ out)
{
    const int idx = blockIdx.x * 256 + threadIdx.x;
    const int b = idx >> 9;
    const int j = idx & 511;
    const int op = b * 1024 + j;
    const int oo = op + 512;

    float ppre = b_p[j] + d_part[0][op] + d_part[1][op] + d_part[2][op] + d_part[3][op];
    float opre = b_o[j] + d_part[0][oo] + d_part[1][oo] + d_part[2][oo] + d_part[3][oo];

    const float p = tanhf(ppre);
    const float o = 1.f / (1.f + expf(-opre));
    out[idx] = o * p;
}

__global__ void k_open(float* __restrict__ o)
{
    o[0] = (float)d_open * (1.f / (float)GATE_ELEMS);
}

// ---------------------------------------------------------------------------
// Trace streamer: HBM-bound, ~1.07 GB traffic, already ~90% of roof.
// ---------------------------------------------------------------------------
__global__ void __launch_bounds__(256) k_traces(
    const float* __restrict__ x,  const float* __restrict__ hl,
    const float* __restrict__ egx, const float* __restrict__ egh,
    const float* __restrict__ erx, const float* __restrict__ erh,
    float* __restrict__ ogx, float* __restrict__ ogh,
    float* __restrict__ orx, float* __restrict__ orh)
{
    const int idx = blockIdx.x * 256 + threadIdx.x;   // 8388608 threads
    const int i   = (idx & 127) << 2;                 // column (float4 aligned)
    const int bj  = idx >> 7;                         // (b,j) flat
    const int b   = bj >> 9;

    const float a  = __ldg(&d_av[bj]);                // uniform per warp -> broadcast
    const float cg = __ldg(&d_cgv[bj]);
    const float cr = __ldg(&d_crv[bj]);

    const float4 xv = *(const float4*)(x  + (b << 9) + i);
    const float4 hv = *(const float4*)(hl + (b << 9) + i);
    const int off = (bj << 9) + i;

    float4 e, t;

    e = *(const float4*)(egx + off);
    t.x = e.x * a + cg * xv.x; t.y = e.y * a + cg * xv.y;
    t.z = e.z * a + cg * xv.z; t.w = e.w * a + cg * xv.w;
    *(float4*)(ogx + off) = t;

    e = *(const float4*)(egh + off);
    t.x = e.x * a + cg * hv.x; t.y = e.y * a + cg * hv.y;
    t.z = e.z * a + cg * hv.z; t.w = e.w * a + cg * hv.w;
    *(float4*)(ogh + off) = t;

    e = *(const float4*)(erx + off);
    t.x = e.x * a + cr * xv.x; t.y = e.y * a + cr * xv.y;
    t.z = e.z * a + cr * xv.z; t.w = e.w * a + cr * xv.w;
    *(float4*)(orx + off) = t;

    e = *(const float4*)(erh + off);
    t.x = e.x * a + cr * hv.x; t.y = e.y * a + cr * hv.y;
    t.z = e.z * a + cr * hv.z; t.w = e.w * a + cr * hv.w;
    *(float4*)(orh + off) = t;
}

// ---------------------------------------------------------------------------
extern "C" void kernel_launch(void* const* d_in, const int* in_sizes, int n_in,
                              void* d_out, int out_size)
{
    const float* x      = (const float*)d_in[0];
    const float* h_last = (const float*)d_in[1];
    const float* w_gx   = (const float*)d_in[2];
    const float* w_gh   = (const float*)d_in[3];
    const float* b_g    = (const float*)d_in[4];
    const float* w_rx   = (const float*)d_in[5];
    const float* w_rh   = (const float*)d_in[6];
    const float* b_r    = (const float*)d_in[7];
    const float* w_px   = (const float*)d_in[8];
    const float* w_ph   = (const float*)d_in[9];
    const float* b_p    = (const float*)d_in[10];
    const float* w_ox   = (const float*)d_in[11];
    const float* w_oh   = (const float*)d_in[12];
    const float* b_o    = (const float*)d_in[13];
    const float* e_w_gx = (const float*)d_in[14];
    const float* e_w_gh = (const float*)d_in[15];
    const float* e_b_g  = (const float*)d_in[16];
    const float* e_w_rx = (const float*)d_in[17];
    const float* e_w_rh = (const float*)d_in[18];
    const float* e_b_r  = (const float*)d_in[19];

    float* out    = (float*)d_out;
    float* o_out  = out;                  // (128,512)
    float* o_h    = out + 65536;          // (128,512)
    float* o_egx  = out + 131072;         // (128,512,512)
    float* o_egh  = out + 33685504;       // (128,512,512)
    float* o_ebg  = out + 67239936;       // (128,512)
    float* o_erx  = out + 67305472;       // (128,512,512)
    float* o_erh  = out + 100859904;      // (128,512,512)
    float* o_ebr  = out + 134414336;      // (128,512)
    float* o_open = out + 134479872;      // scalar

    k_zero<<<1, 1>>>();

    // g/r pre-activations (split-K partials)
    k_gemm<<<dim3(16, 2, NSPLIT), 256>>>(x, h_last, w_gx, w_gh, w_rx, w_rh, 0);

    // gate math, h, e_b updates, openings count
    k_gates<<<GATE_ELEMS / 256, 256>>>(h_last, b_g, b_r, e_b_g, e_b_r,
                                       o_h, o_ebg, o_ebr);

    // p/o pre-activations (uses d_hv computed above)
    k_gemm<<<dim3(16, 2, NSPLIT), 256>>>(x, nullptr, w_px, w_ph, w_ox, w_oh, 1);

    k_out<<<GATE_ELEMS / 256, 256>>>(b_p, b_o, o_out);
    k_open<<<1, 1>>>(o_open);

    // HBM-bound trace streamer: 128*512*512/4 = 8.39M threads
    k_traces<<<(NB * NHID * (NHID / 4)) / 256, 256>>>(
        x, h_last, e_w_gx, e_w_gh, e_w_rx, e_w_rh,
        o_egx, o_egh, o_erx, o_erh);
}

// round 3
// speedup vs baseline: 1.3330x; 1.0952x over previous
#include <cuda_runtime.h>
#include <math.h>

#define NB   128
#define NHID 512
#define GATE_ELEMS (NB * NHID)   // 65536
#define NSPLIT 8
#define GEMM_BLOCKS 256          // 16 n-tiles * 2 m-tiles * 8 splits
#define TRACE_BLOCKS 32768

// ---------------- device scratch (no allocations allowed) ----------------
__device__ float d_part[NSPLIT][NB * 1024];  // split-K partials, 4 MB
__device__ float d_av  [GATE_ELEMS];         // 1 - g
__device__ float d_cgv [GATE_ELEMS];         // dg * delta_h
__device__ float d_crv [GATE_ELEMS];         // dr * g
__device__ float d_hv  [GATE_ELEMS];         // new h
__device__ int   d_cnt [256];                // per-block open counts (k_gates grid)

// ---------------------------------------------------------------------------
// Split-K dual GEMM body: partial[s] = A[128, kchunk] @ W[1024, kchunk]^T
//   Logical C[128,1024]: k halves (x | h), n halves (gate1 | gate2).
//   split s: half = s>>2 selects x/h operands, kb = (s&3)*128 within the half.
// BM=BN=64, BK=16, 256 threads, 4x4 register tile, LDS.128, register prefetch.
// ---------------------------------------------------------------------------
__device__ __forceinline__ void gemm_body(
    const float* __restrict__ Ax, const float* __restrict__ Ah,
    const float* __restrict__ W1x, const float* __restrict__ W1h,
    const float* __restrict__ W2x, const float* __restrict__ W2h,
    int nx, int my, int s, int tid)
{
    __shared__ float As[16][68];   // [k][m], stride 68 floats
    __shared__ float Ws[16][68];   // [k][n]

    const int n0   = nx * 64;               // n in [0,1024)
    const int m0   = my * 64;
    const int half = s >> 2;                 // 0: x-part, 1: h-part
    const int kb   = (s & 3) * 128;          // offset within the 512-wide half

    const bool g2 = (n0 >= 512);
    const int  j0 = g2 ? (n0 - 512) : n0;
    const float* A = half ? Ah : Ax;
    const float* W = g2 ? (half ? W2h : W2x) : (half ? W1h : W1x);
    float* outp    = d_part[s];

    const int lm  = tid & 63;                // tile row (m or n)
    const int lk4 = (tid >> 6) << 2;         // k offset 0,4,8,12

    const int tx = tid & 15;                 // n-dir
    const int ty = tid >> 4;                 // m-dir

    const float* Aload = A + (m0 + lm) * 512 + kb + lk4;
    const float* Wload = W + (j0 + lm) * 512 + kb + lk4;

    float acc[4][4];
    #pragma unroll
    for (int i = 0; i < 4; i++)
        #pragma unroll
        for (int j = 0; j < 4; j++) acc[i][j] = 0.f;

    float4 av = *(const float4*)(Aload);
    float4 wv = *(const float4*)(Wload);

    for (int kt = 0; kt < 128; kt += 16) {
        __syncthreads();
        As[lk4 + 0][lm] = av.x; As[lk4 + 1][lm] = av.y;
        As[lk4 + 2][lm] = av.z; As[lk4 + 3][lm] = av.w;
        Ws[lk4 + 0][lm] = wv.x; Ws[lk4 + 1][lm] = wv.y;
        Ws[lk4 + 2][lm] = wv.z; Ws[lk4 + 3][lm] = wv.w;
        __syncthreads();

        if (kt + 16 < 128) {                 // prefetch next tile
            av = *(const float4*)(Aload + kt + 16);
            wv = *(const float4*)(Wload + kt + 16);
        }

        #pragma unroll
        for (int kk = 0; kk < 16; kk++) {
            const float4 a = *(const float4*)&As[kk][ty << 2];
            const float4 w = *(const float4*)&Ws[kk][tx << 2];
            acc[0][0] = fmaf(a.x, w.x, acc[0][0]);
            acc[0][1] = fmaf(a.x, w.y, acc[0][1]);
            acc[0][2] = fmaf(a.x, w.z, acc[0][2]);
            acc[0][3] = fmaf(a.x, w.w, acc[0][3]);
            acc[1][0] = fmaf(a.y, w.x, acc[1][0]);
            acc[1][1] = fmaf(a.y, w.y, acc[1][1]);
            acc[1][2] = fmaf(a.y, w.z, acc[1][2]);
            acc[1][3] = fmaf(a.y, w.w, acc[1][3]);
            acc[2][0] = fmaf(a.z, w.x, acc[2][0]);
            acc[2][1] = fmaf(a.z, w.y, acc[2][1]);
            acc[2][2] = fmaf(a.z, w.z, acc[2][2]);
            acc[2][3] = fmaf(a.z, w.w, acc[2][3]);
            acc[3][0] = fmaf(a.w, w.x, acc[3][0]);
            acc[3][1] = fmaf(a.w, w.y, acc[3][1]);
            acc[3][2] = fmaf(a.w, w.z, acc[3][2]);
            acc[3][3] = fmaf(a.w, w.w, acc[3][3]);
        }
    }

    #pragma unroll
    for (int i = 0; i < 4; i++) {
        float4 v = make_float4(acc[i][0], acc[i][1], acc[i][2], acc[i][3]);
        *(float4*)(outp + (m0 + (ty << 2) + i) * 1024 + n0 + (tx << 2)) = v;
    }
}

// Trace row update body: idx in [0, 8388608)
__device__ __forceinline__ void trace_body(
    int idx,
    const float* __restrict__ x,  const float* __restrict__ hl,
    const float* __restrict__ egx, const float* __restrict__ egh,
    const float* __restrict__ erx, const float* __restrict__ erh,
    float* __restrict__ ogx, float* __restrict__ ogh,
    float* __restrict__ orx, float* __restrict__ orh)
{
    const int i   = (idx & 127) << 2;                 // column (float4 aligned)
    const int bj  = idx >> 7;                         // (b,j) flat
    const int b   = bj >> 9;

    const float a  = __ldg(&d_av[bj]);                // uniform per warp
    const float cg = __ldg(&d_cgv[bj]);
    const float cr = __ldg(&d_crv[bj]);

    const float4 xv = *(const float4*)(x  + (b << 9) + i);
    const float4 hv = *(const float4*)(hl + (b << 9) + i);
    const int off = (bj << 9) + i;

    float4 e, t;

    e = *(const float4*)(egx + off);
    t.x = e.x * a + cg * xv.x; t.y = e.y * a + cg * xv.y;
    t.z = e.z * a + cg * xv.z; t.w = e.w * a + cg * xv.w;
    *(float4*)(ogx + off) = t;

    e = *(const float4*)(egh + off);
    t.x = e.x * a + cg * hv.x; t.y = e.y * a + cg * hv.y;
    t.z = e.z * a + cg * hv.z; t.w = e.w * a + cg * hv.w;
    *(float4*)(ogh + off) = t;

    e = *(const float4*)(erx + off);
    t.x = e.x * a + cr * xv.x; t.y = e.y * a + cr * xv.y;
    t.z = e.z * a + cr * xv.z; t.w = e.w * a + cr * xv.w;
    *(float4*)(orx + off) = t;

    e = *(const float4*)(erh + off);
    t.x = e.x * a + cr * hv.x; t.y = e.y * a + cr * hv.y;
    t.z = e.z * a + cr * hv.z; t.w = e.w * a + cr * hv.w;
    *(float4*)(orh + off) = t;
}

// ---------------------------------------------------------------------------
// Launch 1: g/r pre-activation GEMM (split-K partials). grid=(16,2,8)
// ---------------------------------------------------------------------------
__global__ void __launch_bounds__(256) k_gemm1(
    const float* __restrict__ x, const float* __restrict__ h_last,
    const float* __restrict__ w_gx, const float* __restrict__ w_gh,
    const float* __restrict__ w_rx, const float* __restrict__ w_rh)
{
    gemm_body(x, h_last, w_gx, w_gh, w_rx, w_rh,
              blockIdx.x, blockIdx.y, blockIdx.z, threadIdx.x);
}

// ---------------------------------------------------------------------------
// Launch 2: gate epilogue — sum partials + bias, gate math, coefficients,
// e_b updates, per-block open counts. grid=256
// ---------------------------------------------------------------------------
__global__ void __launch_bounds__(256) k_gates(
    const float* __restrict__ h_last,
    const float* __restrict__ b_g, const float* __restrict__ b_r,
    const float* __restrict__ e_b_g, const float* __restrict__ e_b_r,
    float* __restrict__ out_h, float* __restrict__ out_ebg, float* __restrict__ out_ebr)
{
    __shared__ int scnt[8];
    const int idx = blockIdx.x * 256 + threadIdx.x;   // b*512 + j
    const int b = idx >> 9;
    const int j = idx & 511;
    const int og  = b * 1024 + j;
    const int orr = og + 512;

    float gpre = b_g[j], rpre = b_r[j];
    #pragma unroll
    for (int s = 0; s < NSPLIT; s++) {
        gpre += d_part[s][og];
        rpre += d_part[s][orr];
    }

    float g = tanhf(gpre);
    g = fmaxf(g, 0.f);                      // relu(tanh)
    const float r  = tanhf(rpre);
    const float hl = h_last[idx];
    const float h  = g * r + (1.f - g) * hl;
    const float Hg = (g > 0.f) ? 1.f : 0.f; // clip(ceil(g),0,1), g in [0,1]
    const float dg = (1.f - g * g) * Hg;
    const float dr = 1.f - r * r;
    const float delta = r - hl;
    const float a  = 1.f - g;
    const float cg = dg * delta;
    const float cr = dr * g;

    d_av[idx]  = a;
    d_cgv[idx] = cg;
    d_crv[idx] = cr;
    d_hv[idx]  = h;

    out_h[idx]   = h;
    out_ebg[idx] = e_b_g[idx] * a + cg;
    out_ebr[idx] = e_b_r[idx] * a + cr;

    const int cnt = __popc(__ballot_sync(0xffffffffu, g > 0.f));
    if ((threadIdx.x & 31) == 0) scnt[threadIdx.x >> 5] = cnt;
    __syncthreads();
    if (threadIdx.x == 0) {
        int t = 0;
        #pragma unroll
        for (int w = 0; w < 8; w++) t += scnt[w];
        d_cnt[blockIdx.x] = t;
    }
}

// ---------------------------------------------------------------------------
// Launch 3: FUSED p/o GEMM + trace streamer.
//   blocks [0, 256)          : GEMM2 (A-h operand = d_hv)
//   blocks [256, 256+32768)  : HBM-bound trace update
// The 256 GEMM CTAs are hidden under ~150us of trace streaming.
// ---------------------------------------------------------------------------
__global__ void __launch_bounds__(256) k_fused(
    const float* __restrict__ x,  const float* __restrict__ h_last,
    const float* __restrict__ w_px, const float* __restrict__ w_ph,
    const float* __restrict__ w_ox, const float* __restrict__ w_oh,
    const float* __restrict__ egx, const float* __restrict__ egh,
    const float* __restrict__ erx, const float* __restrict__ erh,
    float* __restrict__ ogx, float* __restrict__ ogh,
    float* __restrict__ orx, float* __restrict__ orh)
{
    const int bx = blockIdx.x;
    if (bx < GEMM_BLOCKS) {
        const int nx = bx & 15;
        const int my = (bx >> 4) & 1;
        const int s  = bx >> 5;
        gemm_body(x, d_hv, w_px, w_ph, w_ox, w_oh, nx, my, s, threadIdx.x);
    } else {
        const int idx = (bx - GEMM_BLOCKS) * 256 + threadIdx.x;
        trace_body(idx, x, h_last, egx, egh, erx, erh, ogx, ogh, orx, orh);
    }
}

// ---------------------------------------------------------------------------
// Launch 4: out = sigmoid(o_pre) * tanh(p_pre); block 0 also emits openings.
// ---------------------------------------------------------------------------
__global__ void __launch_bounds__(256) k_out(
    const float* __restrict__ b_p, const float* __restrict__ b_o,
    float* __restrict__ out, float* __restrict__ o_open)
{
    const int idx = blockIdx.x * 256 + threadIdx.x;
    const int b = idx >> 9;
    const int j = idx & 511;
    const int op = b * 1024 + j;
    const int oo = op + 512;

    float ppre = b_p[j], opre = b_o[j];
    #pragma unroll
    for (int s = 0; s < NSPLIT; s++) {
        ppre += d_part[s][op];
        opre += d_part[s][oo];
    }

    const float p = tanhf(ppre);
    const float o = 1.f / (1.f + expf(-opre));
    out[idx] = o * p;

    if (blockIdx.x == 0) {
        __shared__ int scnt[256];
        scnt[threadIdx.x] = d_cnt[threadIdx.x];
        __syncthreads();
        for (int st = 128; st > 0; st >>= 1) {
            if (threadIdx.x < st) scnt[threadIdx.x] += scnt[threadIdx.x + st];
            __syncthreads();
        }
        if (threadIdx.x == 0)
            o_open[0] = (float)scnt[0] * (1.f / (float)GATE_ELEMS);
    }
}

// ---------------------------------------------------------------------------
extern "C" void kernel_launch(void* const* d_in, const int* in_sizes, int n_in,
                              void* d_out, int out_size)
{
    const float* x      = (const float*)d_in[0];
    const float* h_last = (const float*)d_in[1];
    const float* w_gx   = (const float*)d_in[2];
    const float* w_gh   = (const float*)d_in[3];
    const float* b_g    = (const float*)d_in[4];
    const float* w_rx   = (const float*)d_in[5];
    const float* w_rh   = (const float*)d_in[6];
    const float* b_r    = (const float*)d_in[7];
    const float* w_px   = (const float*)d_in[8];
    const float* w_ph   = (const float*)d_in[9];
    const float* b_p    = (const float*)d_in[10];
    const float* w_ox   = (const float*)d_in[11];
    const float* w_oh   = (const float*)d_in[12];
    const float* b_o    = (const float*)d_in[13];
    const float* e_w_gx = (const float*)d_in[14];
    const float* e_w_gh = (const float*)d_in[15];
    const float* e_b_g  = (const float*)d_in[16];
    const float* e_w_rx = (const float*)d_in[17];
    const float* e_w_rh = (const float*)d_in[18];
    const float* e_b_r  = (const float*)d_in[19];

    float* out    = (float*)d_out;
    float* o_out  = out;                  // (128,512)
    float* o_h    = out + 65536;          // (128,512)
    float* o_egx  = out + 131072;         // (128,512,512)
    float* o_egh  = out + 33685504;       // (128,512,512)
    float* o_ebg  = out + 67239936;       // (128,512)
    float* o_erx  = out + 67305472;       // (128,512,512)
    float* o_erh  = out + 100859904;      // (128,512,512)
    float* o_ebr  = out + 134414336;      // (128,512)
    float* o_open = out + 134479872;      // scalar

    // g/r pre-activations (split-K=8 partials, 256 CTAs -> 2/SM)
    k_gemm1<<<dim3(16, 2, NSPLIT), 256>>>(x, h_last, w_gx, w_gh, w_rx, w_rh);

    // gate math, h, e_b updates, per-block open counts
    k_gates<<<256, 256>>>(h_last, b_g, b_r, e_b_g, e_b_r, o_h, o_ebg, o_ebr);

    // fused p/o GEMM + HBM trace streamer (GEMM hidden under streaming)
    k_fused<<<GEMM_BLOCKS + TRACE_BLOCKS, 256>>>(
        x, h_last, w_px, w_ph, w_ox, w_oh,
        e_w_gx, e_w_gh, e_w_rx, e_w_rh,
        o_egx, o_egh, o_erx, o_erh);

    // out = sigmoid*tanh + openings scalar
    k_out<<<256, 256>>>(b_p, b_o, o_out, o_open);
}